// round 4
// baseline (speedup 1.0000x reference)
#include <cuda_runtime.h>
#include <cstdint>

#define SEQ   2048
#define HID   512
#define TAPS  64
#define SC    64       // seq rows per CTA
#define UGRP  8        // rows per inner group
#define HTAPS 16       // taps per thread-quarter
#define WSPAN (HTAPS + UGRP - 1)   // 23 live window rows per quarter
#define NPAIR 128      // channel pairs per channel-group
#define HBUF_PAIRS 256 // 512 channels as u64 pairs per row

typedef unsigned long long u64;

__device__ __forceinline__ u64 fma2(u64 a, u64 b, u64 c) {
    u64 d;
    asm("fma.rn.f32x2 %0, %1, %2, %3;" : "=l"(d) : "l"(a), "l"(b), "l"(c));
    return d;
}
__device__ __forceinline__ u64 add2(u64 a, u64 b) {
    u64 d;
    asm("add.rn.f32x2 %0, %1, %2;" : "=l"(d) : "l"(a), "l"(b));
    return d;
}
__device__ __forceinline__ float lo32(u64 v) { return __uint_as_float((unsigned)v); }
__device__ __forceinline__ float hi32(u64 v) { return __uint_as_float((unsigned)(v >> 32)); }
__device__ __forceinline__ u64 pack2(float l, float h) {
    return ((u64)__float_as_uint(h) << 32) | (u64)__float_as_uint(l);
}

// Fused circular depthwise conv (64 taps, f32x2) + residual + LayerNorm.
// 512 threads = 128 channel-pairs x 4 tap-quarters. Two 256-channel passes.
// Dynamic smem: hbuf[64][256] (128KB) + part[2][3][8][128] (48KB) = 176KB.
extern __shared__ u64 dsm[];

__global__ __launch_bounds__(512, 1) void fconv_ln_kernel(
    const float* __restrict__ x,
    const float* __restrict__ w,
    const float* __restrict__ gamma,
    const float* __restrict__ beta,
    float* __restrict__ out)
{
    u64* hbuf = dsm;                          // [SC][HBUF_PAIRS]
    u64* part = dsm + SC * HBUF_PAIRS;        // [2][3][UGRP][NPAIR]

    const int tid = threadIdx.x;
    const int p   = tid & (NPAIR - 1);        // channel pair within group
    const int q   = tid >> 7;                 // tap quarter: taps [16q, 16q+16)
    const int b   = blockIdx.y;
    const int s0  = blockIdx.x * SC;

    const float ks = 0.022097086912079608f;   // 1/sqrt(2048)
    const u64 sc2 = pack2(ks, ks);

#pragma unroll 1
    for (int cg = 0; cg < 2; ++cg) {
        const int c = cg * 256 + p * 2;
        const u64* __restrict__ xb =
            reinterpret_cast<const u64*>(x + (size_t)b * (SEQ * HID) + c);
        const int slotc = cg * NPAIR + p;

        // This quarter's 16 tap-weights for this channel pair.
        u64 wr[HTAPS];
#pragma unroll
        for (int t = 0; t < HTAPS; ++t)
            wr[t] = *reinterpret_cast<const u64*>(w + (t + HTAPS * q) * HID + c);

        // Window: win[i] = x[(s0 - 16q - 15 + i) mod SEQ], i in [0,23)
        u64 win[WSPAN];
#pragma unroll
        for (int i = 0; i < WSPAN; ++i) {
            int row = (s0 + SEQ - HTAPS * q - (HTAPS - 1) + i) & (SEQ - 1);
            win[i] = xb[row * (HID / 2)];
        }

#pragma unroll
        for (int g = 0; g < SC / UGRP; ++g) {
            const int sb = s0 + g * UGRP;
            const int rl = g * UGRP;
            const int buf = g & 1;

            // Prefetch the next UGRP window rows (land during compute).
            u64 nxt[UGRP];
#pragma unroll
            for (int i = 0; i < UGRP; ++i) {
                int row = (sb + SEQ - HTAPS * q + UGRP + i) & (SEQ - 1);
                nxt[i] = xb[row * (HID / 2)];
            }

            // 16-tap partials for UGRP rows: acc[j] = sum_t wr[t]*win[15+j-t]
            u64 acc[UGRP];
#pragma unroll
            for (int j = 0; j < UGRP; ++j) acc[j] = 0ull;
#pragma unroll
            for (int t = 0; t < HTAPS; ++t) {
#pragma unroll
                for (int j = 0; j < UGRP; ++j)
                    acc[j] = fma2(wr[t], win[HTAPS - 1 + j - t], acc[j]);
            }

            if (q) {
                u64* pp = part + ((buf * 3 + (q - 1)) * UGRP) * NPAIR + p;
#pragma unroll
                for (int j = 0; j < UGRP; ++j) pp[j * NPAIR] = acc[j];
            }
            __syncthreads();
            if (!q) {
                const u64* p0 = part + (buf * 3 * UGRP) * NPAIR + p;
#pragma unroll
                for (int j = 0; j < UGRP; ++j) {
                    u64 tot = add2(add2(acc[j], p0[j * NPAIR]),
                                   add2(p0[(UGRP + j) * NPAIR],
                                        p0[(2 * UGRP + j) * NPAIR]));
                    // residual = x[sb+j] = win[15+j] for quarter 0
                    hbuf[(rl + j) * HBUF_PAIRS + slotc] =
                        fma2(tot, sc2, win[HTAPS - 1 + j]);
                }
            }

            // Slide window by UGRP (renamed away by full unroll).
#pragma unroll
            for (int i = 0; i < WSPAN - UGRP; ++i) win[i] = win[i + UGRP];
#pragma unroll
            for (int i = 0; i < UGRP; ++i) win[WSPAN - UGRP + i] = nxt[i];
        }
    }
    __syncthreads();

    // ---- LayerNorm epilogue: 16 warps, 4 rows each ----
    const int wid  = tid >> 5;
    const int lane = tid & 31;

    u64 g8[8], b8[8];
#pragma unroll
    for (int k = 0; k < 8; ++k) {
        g8[k] = reinterpret_cast<const u64*>(gamma)[lane + 32 * k];
        b8[k] = reinterpret_cast<const u64*>(beta)[lane + 32 * k];
    }

    float* __restrict__ ob = out + (size_t)b * (SEQ * HID) + (size_t)s0 * HID;

#pragma unroll
    for (int rr = 0; rr < SC / 16; ++rr) {
        const int r = wid + rr * 16;
        u64 v[8];
        float s = 0.f, qq = 0.f;
#pragma unroll
        for (int k = 0; k < 8; ++k) {
            v[k] = hbuf[r * HBUF_PAIRS + lane + 32 * k];
            float a = lo32(v[k]), bb = hi32(v[k]);
            s += a + bb;
            qq += a * a + bb * bb;
        }
#pragma unroll
        for (int o = 16; o > 0; o >>= 1) {
            s  += __shfl_xor_sync(0xFFFFFFFFu, s, o);
            qq += __shfl_xor_sync(0xFFFFFFFFu, qq, o);
        }
        const float mean = s * (1.0f / HID);
        const float var  = qq * (1.0f / HID) - mean * mean;
        const float inv  = rsqrtf(var + 1e-12f);

        u64* __restrict__ orow = reinterpret_cast<u64*>(ob + r * HID);
#pragma unroll
        for (int k = 0; k < 8; ++k) {
            float a  = (lo32(v[k]) - mean) * inv;
            float bb = (hi32(v[k]) - mean) * inv;
            orow[lane + 32 * k] =
                pack2(lo32(g8[k]) * a + lo32(b8[k]),
                      hi32(g8[k]) * bb + hi32(b8[k]));
        }
    }
}

extern "C" void kernel_launch(void* const* d_in, const int* in_sizes, int n_in,
                              void* d_out, int out_size)
{
    const float* x     = (const float*)d_in[0];   // [B, 2048, 512] f32
    const float* w     = (const float*)d_in[1];   // [1, 64, 512]   f32
    const float* gamma = (const float*)d_in[2];   // [512]          f32
    const float* beta  = (const float*)d_in[3];   // [512]          f32
    float* out = (float*)d_out;

    const int B = in_sizes[0] / (SEQ * HID);
    const int smem = (SC * HBUF_PAIRS + 2 * 3 * UGRP * NPAIR) * sizeof(u64); // 176KB

    static bool attr_set = false;
    if (!attr_set) {
        cudaFuncSetAttribute(fconv_ln_kernel,
                             cudaFuncAttributeMaxDynamicSharedMemorySize, smem);
        attr_set = true;
    }

    dim3 grid(SEQ / SC, B);   // (32, B)
    fconv_ln_kernel<<<grid, 512, smem>>>(x, w, gamma, beta, out);
}